// round 6
// baseline (speedup 1.0000x reference)
#include <cuda_runtime.h>

// Problem constants
#define BB 2
#define TT 5
#define NN 4096
#define CC 16
#define DD 128
#define NS 16384          // (T-1)*N
#define MM 8192           // B*N
#define NSAMP 4
#define WPB1 4
#define NBLK1 (MM / WPB1)   // 2048
#define ROWS3 16
#define NBLK3 (MM / ROWS3)  // 512
#define EPSF 1e-5f

// -------- scratch (device globals; no allocation allowed) --------
__device__ float d_hmax[MM * DD];
__device__ float d_hmin[MM * DD];
__device__ float d_ps1[DD * NBLK1];   // [o][blk] partial sums
__device__ float d_pq1[DD * NBLK1];   // [o][blk] partial sumsq
__device__ float d_scale1[DD];
__device__ float d_shift1[DD];
__device__ float d_y[3 * MM * DD];
__device__ float d_ps2[3 * DD * NBLK3];  // [(k*128+o)][blk]
__device__ float d_pq2[3 * DD * NBLK3];
__device__ float d_scale2[3 * DD];
__device__ float d_shift2[3 * DD];

// ============================================================================
// K1: ball query (first-4-by-index within radius) + conv1 + per-block BN stats
// One warp per query. Early-exit scan, 256 candidates per iteration (MLP=8).
// ============================================================================
__global__ __launch_bounds__(128) void k1_ball_conv(
    const float* __restrict__ x,
    const float* __restrict__ conv_w,   // (128,16)
    const float* __restrict__ conv_b)   // (128,)
{
    __shared__ float Wt_s[16 * 128];    // transposed [c][o] -> conflict-free reads
    __shared__ float bias_s[128];
    __shared__ float g_s[WPB1][64];     // per-warp grouped feats [c][s]
    __shared__ float ps_s[WPB1][128];
    __shared__ float pq_s[WPB1][128];

    const int tid = threadIdx.x;

    // cooperative weight/bias load (transpose W)
    #pragma unroll
    for (int f = tid; f < 2048; f += 128) {
        int o = f >> 4, c = f & 15;
        Wt_s[c * 128 + o] = conv_w[f];
    }
    bias_s[tid] = conv_b[tid];
    __syncthreads();

    const int wid = tid >> 5, lane = tid & 31;
    const int m = blockIdx.x * WPB1 + wid;     // query id in [0, 8192)
    const int b = m >> 12, i = m & 4095;

    // query point = x[b][0][i][0:3]  (rows are 16 floats = 4 float4, 64B aligned)
    const float4* x4 = (const float4*)x;
    float4 q4 = x4[(size_t)((b * TT + 0) * NN + i) * 4];
    const float qx = q4.x, qy = q4.y, qz = q4.z;
    // exact (non-fma) arithmetic to mirror reference:  (qq+pp) - 2*dot
    const float qq = __fadd_rn(__fadd_rn(__fmul_rn(qx, qx), __fmul_rn(qy, qy)),
                               __fmul_rn(qz, qz));

    const float4* xb = x4 + (size_t)((b * TT + 1) * NN) * 4;  // t=1.. rows

    int cnt = 0;
    int i0 = 0, i1 = 0, i2 = 0, i3 = 0;
    const int U = 8;
    for (int base = 0; base < NS && cnt < NSAMP; base += 32 * U) {
        float d2v[U];
        #pragma unroll
        for (int u = 0; u < U; u++) {
            int j = base + u * 32 + lane;
            float4 p = xb[(size_t)j * 4];
            float pp = __fadd_rn(__fadd_rn(__fmul_rn(p.x, p.x), __fmul_rn(p.y, p.y)),
                                 __fmul_rn(p.z, p.z));
            float dt = __fadd_rn(__fadd_rn(__fmul_rn(qx, p.x), __fmul_rn(qy, p.y)),
                                 __fmul_rn(qz, p.z));
            d2v[u] = __fsub_rn(__fadd_rn(qq, pp), __fmul_rn(2.0f, dt));
        }
        #pragma unroll
        for (int u = 0; u < U; u++) {
            unsigned msk = __ballot_sync(0xffffffffu, d2v[u] < 1.0f);
            while (msk && cnt < NSAMP) {
                int l = __ffs(msk) - 1;
                msk &= msk - 1;
                int j = base + u * 32 + l;
                if (cnt == 0) i0 = j;
                else if (cnt == 1) i1 = j;
                else if (cnt == 2) i2 = j;
                else i3 = j;
                cnt++;
            }
        }
    }

    const bool empty = (cnt == 0);
    if (cnt < 2) i1 = i0;
    if (cnt < 3) i2 = i0;
    if (cnt < 4) i3 = i0;

    // gather 4 feature rows (16 floats each) into smem as g[c][s]
    if (lane < 4) {
        int j = (lane == 0) ? i0 : (lane == 1) ? i1 : (lane == 2) ? i2 : i3;
        const float4* row = xb + (size_t)j * 4;
        #pragma unroll
        for (int part = 0; part < 4; part++) {
            float4 v = row[part];
            if (empty) { v.x = 0.f; v.y = 0.f; v.z = 0.f; v.w = 0.f; }
            g_s[wid][(4 * part + 0) * 4 + lane] = v.x;
            g_s[wid][(4 * part + 1) * 4 + lane] = v.y;
            g_s[wid][(4 * part + 2) * 4 + lane] = v.z;
            g_s[wid][(4 * part + 3) * 4 + lane] = v.w;
        }
    }
    __syncwarp();

    // load g into registers (broadcast LDS.128)
    float4 g4[16];
    #pragma unroll
    for (int c = 0; c < 16; c++)
        g4[c] = *(const float4*)&g_s[wid][c * 4];

    // conv: lane handles channels {lane, lane+32, lane+64, lane+96}
    #pragma unroll
    for (int qc = 0; qc < 4; qc++) {
        int o = lane + 32 * qc;
        float b0 = bias_s[o];
        float h0 = b0, h1 = b0, h2 = b0, h3 = b0;
        #pragma unroll
        for (int c = 0; c < 16; c++) {
            float wv = Wt_s[c * 128 + o];
            h0 = fmaf(wv, g4[c].x, h0);
            h1 = fmaf(wv, g4[c].y, h1);
            h2 = fmaf(wv, g4[c].z, h2);
            h3 = fmaf(wv, g4[c].w, h3);
        }
        float mx = fmaxf(fmaxf(h0, h1), fmaxf(h2, h3));
        float mn = fminf(fminf(h0, h1), fminf(h2, h3));
        d_hmax[(size_t)m * 128 + o] = mx;
        d_hmin[(size_t)m * 128 + o] = mn;
        ps_s[wid][o] = ((h0 + h1) + (h2 + h3));
        pq_s[wid][o] = ((h0 * h0 + h1 * h1) + (h2 * h2 + h3 * h3));
    }
    __syncthreads();

    // deterministic block partial: fixed summation order over 4 warps
    {
        float s = ((ps_s[0][tid] + ps_s[1][tid]) + (ps_s[2][tid] + ps_s[3][tid]));
        float q2 = ((pq_s[0][tid] + pq_s[1][tid]) + (pq_s[2][tid] + pq_s[3][tid]));
        d_ps1[(size_t)tid * NBLK1 + blockIdx.x] = s;
        d_pq1[(size_t)tid * NBLK1 + blockIdx.x] = q2;
    }
}

// ============================================================================
// K2: finalize BN1 stats (per channel over M*4 samples)
// ============================================================================
__global__ __launch_bounds__(256) void k2_finalize1(
    const float* __restrict__ bn_g, const float* __restrict__ bn_b)
{
    const int o = blockIdx.x;
    const int t = threadIdx.x;
    __shared__ float ss[256], sq[256];
    float a = 0.f, c2 = 0.f;
    for (int i = t; i < NBLK1; i += 256) {
        a += d_ps1[(size_t)o * NBLK1 + i];
        c2 += d_pq1[(size_t)o * NBLK1 + i];
    }
    ss[t] = a; sq[t] = c2;
    __syncthreads();
    for (int st = 128; st > 0; st >>= 1) {
        if (t < st) { ss[t] += ss[t + st]; sq[t] += sq[t + st]; }
        __syncthreads();
    }
    if (t == 0) {
        const float n = (float)(MM * 4);
        float mean = ss[0] / n;
        float var = sq[0] / n - mean * mean;
        float sc = bn_g[o] * rsqrtf(var + EPSF);
        d_scale1[o] = sc;
        d_shift1[o] = bn_b[o] - mean * sc;
    }
}

// ============================================================================
// K3: h_bn = BN1(max) (feature output) + 3x GEMM (8192x128x128) + BN2 partials
// 16 rows per block, 128 threads (thread = output channel).
// ============================================================================
__global__ __launch_bounds__(128) void k3_gemm(
    const float* __restrict__ w1, const float* __restrict__ b1,
    const float* __restrict__ w2, const float* __restrict__ b2,
    const float* __restrict__ w3, const float* __restrict__ b3,
    float* __restrict__ out_feature)
{
    __shared__ float hb[ROWS3][128];
    const int tid = threadIdx.x;
    const int blk = blockIdx.x;
    const int m0 = blk * ROWS3;

    const float sc = d_scale1[tid], sh = d_shift1[tid];
    #pragma unroll
    for (int r = 0; r < ROWS3; r++) {
        size_t m = (size_t)(m0 + r);
        float v = (sc >= 0.f) ? d_hmax[m * 128 + tid] : d_hmin[m * 128 + tid];
        float hv = fmaf(sc, v, sh);
        hb[r][tid] = hv;
        out_feature[m * 128 + tid] = hv;
    }
    __syncthreads();

    const float* Ws[3] = { w1, w2, w3 };
    const float* Bs[3] = { b1, b2, b3 };
    #pragma unroll
    for (int k = 0; k < 3; k++) {
        float acc[ROWS3];
        const float bk = Bs[k][tid];
        #pragma unroll
        for (int r = 0; r < ROWS3; r++) acc[r] = bk;
        const float* wr = Ws[k] + (size_t)tid * 128;
        #pragma unroll 4
        for (int c = 0; c < 128; c += 4) {
            float4 w4 = *(const float4*)(wr + c);
            #pragma unroll
            for (int r = 0; r < ROWS3; r++) {
                float4 h4 = *(const float4*)&hb[r][c];
                acc[r] = fmaf(w4.x, h4.x, acc[r]);
                acc[r] = fmaf(w4.y, h4.y, acc[r]);
                acc[r] = fmaf(w4.z, h4.z, acc[r]);
                acc[r] = fmaf(w4.w, h4.w, acc[r]);
            }
        }
        float s = 0.f, q2 = 0.f;
        #pragma unroll
        for (int r = 0; r < ROWS3; r++) {
            d_y[((size_t)k * MM + (m0 + r)) * 128 + tid] = acc[r];
            s += acc[r];
            q2 += acc[r] * acc[r];
        }
        d_ps2[((size_t)k * 128 + tid) * NBLK3 + blk] = s;
        d_pq2[((size_t)k * 128 + tid) * NBLK3 + blk] = q2;
    }
}

// ============================================================================
// K4: finalize BN2 stats (per (head, channel) over M samples)
// ============================================================================
__global__ __launch_bounds__(128) void k4_finalize2(
    const float* __restrict__ bn_g, const float* __restrict__ bn_b)
{
    const int ch = blockIdx.x;       // 0..383
    const int t = threadIdx.x;       // 128
    __shared__ float ss[128], sq[128];
    float a = 0.f, c2 = 0.f;
    for (int i = t; i < NBLK3; i += 128) {
        a += d_ps2[(size_t)ch * NBLK3 + i];
        c2 += d_pq2[(size_t)ch * NBLK3 + i];
    }
    ss[t] = a; sq[t] = c2;
    __syncthreads();
    for (int st = 64; st > 0; st >>= 1) {
        if (t < st) { ss[t] += ss[t + st]; sq[t] += sq[t + st]; }
        __syncthreads();
    }
    if (t == 0) {
        const float n = (float)MM;
        float mean = ss[0] / n;
        float var = sq[0] / n - mean * mean;
        int o = ch & 127;
        float sc = bn_g[o] * rsqrtf(var + EPSF);
        d_scale2[ch] = sc;
        d_shift2[ch] = bn_b[o] - mean * sc;
    }
}

// ============================================================================
// K5: relu(BN2(y)) then 7 head dot-products per row; warp per row.
// ============================================================================
__global__ __launch_bounds__(256) void k5_heads(
    const float* __restrict__ ce_w, const float* __restrict__ ce_b,
    const float* __restrict__ lwh_w, const float* __restrict__ lwh_b,
    const float* __restrict__ th_w, const float* __restrict__ th_b,
    float* __restrict__ out)
{
    __shared__ float hw[7][128];
    __shared__ float hbias[7];
    const int tid = threadIdx.x;
    for (int f = tid; f < 7 * 128; f += 256) {
        int r = f >> 7, c = f & 127;
        float v = (r < 3) ? ce_w[r * 128 + c]
                : (r < 6) ? lwh_w[(r - 3) * 128 + c]
                          : th_w[c];
        hw[r][c] = v;
    }
    if (tid < 7)
        hbias[tid] = (tid < 3) ? ce_b[tid] : (tid < 6) ? lwh_b[tid - 3] : th_b[0];
    __syncthreads();

    const int wid = tid >> 5, lane = tid & 31;
    const int m = blockIdx.x * 8 + wid;

    float p0 = 0.f, p1 = 0.f, p2 = 0.f, p3 = 0.f, p4 = 0.f, p5 = 0.f, p6 = 0.f;
    #pragma unroll
    for (int k = 0; k < 3; k++) {
        #pragma unroll
        for (int q = 0; q < 4; q++) {
            int o = lane + 32 * q;
            float v = d_y[((size_t)k * MM + m) * 128 + o];
            float xv = fmaxf(0.f, fmaf(d_scale2[k * 128 + o], v, d_shift2[k * 128 + o]));
            if (k == 0) {
                p0 = fmaf(xv, hw[0][o], p0);
                p1 = fmaf(xv, hw[1][o], p1);
                p2 = fmaf(xv, hw[2][o], p2);
            } else if (k == 1) {
                p3 = fmaf(xv, hw[3][o], p3);
                p4 = fmaf(xv, hw[4][o], p4);
                p5 = fmaf(xv, hw[5][o], p5);
            } else {
                p6 = fmaf(xv, hw[6][o], p6);
            }
        }
    }
    float pr[7] = { p0, p1, p2, p3, p4, p5, p6 };
    #pragma unroll
    for (int j = 0; j < 7; j++) {
        float v = pr[j];
        #pragma unroll
        for (int st = 16; st > 0; st >>= 1)
            v += __shfl_down_sync(0xffffffffu, v, st);
        if (lane == 0)
            out[(size_t)m * 7 + j] = v + hbias[j];
    }
}

// ============================================================================
extern "C" void kernel_launch(void* const* d_in, const int* in_sizes, int n_in,
                              void* d_out, int out_size)
{
    const float* x       = (const float*)d_in[0];
    const float* conv1_w = (const float*)d_in[1];
    const float* conv1_b = (const float*)d_in[2];
    const float* bn_g    = (const float*)d_in[3];
    const float* bn_b    = (const float*)d_in[4];
    const float* fc1_w   = (const float*)d_in[5];
    const float* fc1_b   = (const float*)d_in[6];
    const float* ce_w    = (const float*)d_in[7];
    const float* ce_b    = (const float*)d_in[8];
    const float* fc2_w   = (const float*)d_in[9];
    const float* fc2_b   = (const float*)d_in[10];
    const float* lwh_w   = (const float*)d_in[11];
    const float* lwh_b   = (const float*)d_in[12];
    const float* fc3_w   = (const float*)d_in[13];
    const float* fc3_b   = (const float*)d_in[14];
    const float* th_w    = (const float*)d_in[15];
    const float* th_b    = (const float*)d_in[16];

    float* out  = (float*)d_out;          // (B,N,7) flattened
    float* feat = out + (size_t)MM * 7;   // (B,N,128) flattened

    k1_ball_conv<<<NBLK1, 128>>>(x, conv1_w, conv1_b);
    k2_finalize1<<<128, 256>>>(bn_g, bn_b);
    k3_gemm<<<NBLK3, 128>>>(fc1_w, fc1_b, fc2_w, fc2_b, fc3_w, fc3_b, feat);
    k4_finalize2<<<384, 128>>>(bn_g, bn_b);
    k5_heads<<<MM / 8, 256>>>(ce_w, ce_b, lwh_w, lwh_b, th_w, th_b, out);
}

// round 7
// speedup vs baseline: 1.0021x; 1.0021x over previous
#include <cuda_runtime.h>

// Problem constants
#define BB 2
#define TT 5
#define NN 4096
#define CC 16
#define DD 128
#define NS 16384          // (T-1)*N
#define MM 8192           // B*N
#define NSAMP 4
#define WPB1 4
#define NBLK1 (MM / WPB1)   // 2048
#define ROWS3 16
#define NBLK3 (MM / ROWS3)  // 512
#define EPSF 1e-5f

// -------- scratch (device globals; no allocation allowed) --------
__device__ float d_hmax[MM * DD];
__device__ float d_hmin[MM * DD];
__device__ float d_ps1[DD * NBLK1];   // [o][blk] partial sums
__device__ float d_pq1[DD * NBLK1];   // [o][blk] partial sumsq
__device__ float d_scale1[DD];
__device__ float d_shift1[DD];
__device__ float d_y[3 * MM * DD];
__device__ float d_ps2[3 * DD * NBLK3];  // [(k*128+o)][blk]
__device__ float d_pq2[3 * DD * NBLK3];
__device__ float d_scale2[3 * DD];
__device__ float d_shift2[3 * DD];

// ============================================================================
// K1: ball query (first-4-by-index within radius) + conv1 + per-block BN stats
// One warp per query. Early-exit scan, 256 candidates per iteration (MLP=8).
// ============================================================================
__global__ __launch_bounds__(128) void k1_ball_conv(
    const float* __restrict__ x,
    const float* __restrict__ conv_w,   // (128,16)
    const float* __restrict__ conv_b)   // (128,)
{
    __shared__ float Wt_s[16 * 128];    // transposed [c][o] -> conflict-free reads
    __shared__ float bias_s[128];
    __shared__ float g_s[WPB1][64];     // per-warp grouped feats [c][s]
    __shared__ float ps_s[WPB1][128];
    __shared__ float pq_s[WPB1][128];

    const int tid = threadIdx.x;

    // cooperative weight/bias load (transpose W)
    #pragma unroll
    for (int f = tid; f < 2048; f += 128) {
        int o = f >> 4, c = f & 15;
        Wt_s[c * 128 + o] = conv_w[f];
    }
    bias_s[tid] = conv_b[tid];
    __syncthreads();

    const int wid = tid >> 5, lane = tid & 31;
    const int m = blockIdx.x * WPB1 + wid;     // query id in [0, 8192)
    const int b = m >> 12, i = m & 4095;

    // query point = x[b][0][i][0:3]  (rows are 16 floats = 4 float4, 64B aligned)
    const float4* x4 = (const float4*)x;
    float4 q4 = x4[(size_t)((b * TT + 0) * NN + i) * 4];
    const float qx = q4.x, qy = q4.y, qz = q4.z;
    // exact (non-fma) arithmetic to mirror reference:  (qq+pp) - 2*dot
    const float qq = __fadd_rn(__fadd_rn(__fmul_rn(qx, qx), __fmul_rn(qy, qy)),
                               __fmul_rn(qz, qz));

    const float4* xb = x4 + (size_t)((b * TT + 1) * NN) * 4;  // t=1.. rows

    int cnt = 0;
    int i0 = 0, i1 = 0, i2 = 0, i3 = 0;
    const int U = 8;
    for (int base = 0; base < NS && cnt < NSAMP; base += 32 * U) {
        float d2v[U];
        #pragma unroll
        for (int u = 0; u < U; u++) {
            int j = base + u * 32 + lane;
            float4 p = xb[(size_t)j * 4];
            float pp = __fadd_rn(__fadd_rn(__fmul_rn(p.x, p.x), __fmul_rn(p.y, p.y)),
                                 __fmul_rn(p.z, p.z));
            float dt = __fadd_rn(__fadd_rn(__fmul_rn(qx, p.x), __fmul_rn(qy, p.y)),
                                 __fmul_rn(qz, p.z));
            d2v[u] = __fsub_rn(__fadd_rn(qq, pp), __fmul_rn(2.0f, dt));
        }
        #pragma unroll
        for (int u = 0; u < U; u++) {
            unsigned msk = __ballot_sync(0xffffffffu, d2v[u] < 1.0f);
            while (msk && cnt < NSAMP) {
                int l = __ffs(msk) - 1;
                msk &= msk - 1;
                int j = base + u * 32 + l;
                if (cnt == 0) i0 = j;
                else if (cnt == 1) i1 = j;
                else if (cnt == 2) i2 = j;
                else i3 = j;
                cnt++;
            }
        }
    }

    const bool empty = (cnt == 0);
    if (cnt < 2) i1 = i0;
    if (cnt < 3) i2 = i0;
    if (cnt < 4) i3 = i0;

    // gather 4 feature rows (16 floats each) into smem as g[c][s]
    if (lane < 4) {
        int j = (lane == 0) ? i0 : (lane == 1) ? i1 : (lane == 2) ? i2 : i3;
        const float4* row = xb + (size_t)j * 4;
        #pragma unroll
        for (int part = 0; part < 4; part++) {
            float4 v = row[part];
            if (empty) { v.x = 0.f; v.y = 0.f; v.z = 0.f; v.w = 0.f; }
            g_s[wid][(4 * part + 0) * 4 + lane] = v.x;
            g_s[wid][(4 * part + 1) * 4 + lane] = v.y;
            g_s[wid][(4 * part + 2) * 4 + lane] = v.z;
            g_s[wid][(4 * part + 3) * 4 + lane] = v.w;
        }
    }
    __syncwarp();

    // load g into registers (broadcast LDS.128)
    float4 g4[16];
    #pragma unroll
    for (int c = 0; c < 16; c++)
        g4[c] = *(const float4*)&g_s[wid][c * 4];

    // conv: lane handles channels {lane, lane+32, lane+64, lane+96}
    #pragma unroll
    for (int qc = 0; qc < 4; qc++) {
        int o = lane + 32 * qc;
        float b0 = bias_s[o];
        float h0 = b0, h1 = b0, h2 = b0, h3 = b0;
        #pragma unroll
        for (int c = 0; c < 16; c++) {
            float wv = Wt_s[c * 128 + o];
            h0 = fmaf(wv, g4[c].x, h0);
            h1 = fmaf(wv, g4[c].y, h1);
            h2 = fmaf(wv, g4[c].z, h2);
            h3 = fmaf(wv, g4[c].w, h3);
        }
        float mx = fmaxf(fmaxf(h0, h1), fmaxf(h2, h3));
        float mn = fminf(fminf(h0, h1), fminf(h2, h3));
        d_hmax[(size_t)m * 128 + o] = mx;
        d_hmin[(size_t)m * 128 + o] = mn;
        ps_s[wid][o] = ((h0 + h1) + (h2 + h3));
        pq_s[wid][o] = ((h0 * h0 + h1 * h1) + (h2 * h2 + h3 * h3));
    }
    __syncthreads();

    // deterministic block partial: fixed summation order over 4 warps
    {
        float s = ((ps_s[0][tid] + ps_s[1][tid]) + (ps_s[2][tid] + ps_s[3][tid]));
        float q2 = ((pq_s[0][tid] + pq_s[1][tid]) + (pq_s[2][tid] + pq_s[3][tid]));
        d_ps1[(size_t)tid * NBLK1 + blockIdx.x] = s;
        d_pq1[(size_t)tid * NBLK1 + blockIdx.x] = q2;
    }
}

// ============================================================================
// K2: finalize BN1 stats (per channel over M*4 samples)
// ============================================================================
__global__ __launch_bounds__(256) void k2_finalize1(
    const float* __restrict__ bn_g, const float* __restrict__ bn_b)
{
    const int o = blockIdx.x;
    const int t = threadIdx.x;
    __shared__ float ss[256], sq[256];
    float a = 0.f, c2 = 0.f;
    for (int i = t; i < NBLK1; i += 256) {
        a += d_ps1[(size_t)o * NBLK1 + i];
        c2 += d_pq1[(size_t)o * NBLK1 + i];
    }
    ss[t] = a; sq[t] = c2;
    __syncthreads();
    for (int st = 128; st > 0; st >>= 1) {
        if (t < st) { ss[t] += ss[t + st]; sq[t] += sq[t + st]; }
        __syncthreads();
    }
    if (t == 0) {
        const float n = (float)(MM * 4);
        float mean = ss[0] / n;
        float var = sq[0] / n - mean * mean;
        float sc = bn_g[o] * rsqrtf(var + EPSF);
        d_scale1[o] = sc;
        d_shift1[o] = bn_b[o] - mean * sc;
    }
}

// ============================================================================
// K3: h_bn = BN1(max) (feature output) + 3x GEMM (8192x128x128) + BN2 partials
// 16 rows per block, 128 threads (thread = output channel).
// ============================================================================
__global__ __launch_bounds__(128) void k3_gemm(
    const float* __restrict__ w1, const float* __restrict__ b1,
    const float* __restrict__ w2, const float* __restrict__ b2,
    const float* __restrict__ w3, const float* __restrict__ b3,
    float* __restrict__ out_feature)
{
    __shared__ float hb[ROWS3][128];
    const int tid = threadIdx.x;
    const int blk = blockIdx.x;
    const int m0 = blk * ROWS3;

    const float sc = d_scale1[tid], sh = d_shift1[tid];
    #pragma unroll
    for (int r = 0; r < ROWS3; r++) {
        size_t m = (size_t)(m0 + r);
        float v = (sc >= 0.f) ? d_hmax[m * 128 + tid] : d_hmin[m * 128 + tid];
        float hv = fmaf(sc, v, sh);
        hb[r][tid] = hv;
        out_feature[m * 128 + tid] = hv;
    }
    __syncthreads();

    const float* Ws[3] = { w1, w2, w3 };
    const float* Bs[3] = { b1, b2, b3 };
    #pragma unroll
    for (int k = 0; k < 3; k++) {
        float acc[ROWS3];
        const float bk = Bs[k][tid];
        #pragma unroll
        for (int r = 0; r < ROWS3; r++) acc[r] = bk;
        const float* wr = Ws[k] + (size_t)tid * 128;
        #pragma unroll 4
        for (int c = 0; c < 128; c += 4) {
            float4 w4 = *(const float4*)(wr + c);
            #pragma unroll
            for (int r = 0; r < ROWS3; r++) {
                float4 h4 = *(const float4*)&hb[r][c];
                acc[r] = fmaf(w4.x, h4.x, acc[r]);
                acc[r] = fmaf(w4.y, h4.y, acc[r]);
                acc[r] = fmaf(w4.z, h4.z, acc[r]);
                acc[r] = fmaf(w4.w, h4.w, acc[r]);
            }
        }
        float s = 0.f, q2 = 0.f;
        #pragma unroll
        for (int r = 0; r < ROWS3; r++) {
            d_y[((size_t)k * MM + (m0 + r)) * 128 + tid] = acc[r];
            s += acc[r];
            q2 += acc[r] * acc[r];
        }
        d_ps2[((size_t)k * 128 + tid) * NBLK3 + blk] = s;
        d_pq2[((size_t)k * 128 + tid) * NBLK3 + blk] = q2;
    }
}

// ============================================================================
// K4: finalize BN2 stats (per (head, channel) over M samples)
// ============================================================================
__global__ __launch_bounds__(128) void k4_finalize2(
    const float* __restrict__ bn_g, const float* __restrict__ bn_b)
{
    const int ch = blockIdx.x;       // 0..383
    const int t = threadIdx.x;       // 128
    __shared__ float ss[128], sq[128];
    float a = 0.f, c2 = 0.f;
    for (int i = t; i < NBLK3; i += 128) {
        a += d_ps2[(size_t)ch * NBLK3 + i];
        c2 += d_pq2[(size_t)ch * NBLK3 + i];
    }
    ss[t] = a; sq[t] = c2;
    __syncthreads();
    for (int st = 64; st > 0; st >>= 1) {
        if (t < st) { ss[t] += ss[t + st]; sq[t] += sq[t + st]; }
        __syncthreads();
    }
    if (t == 0) {
        const float n = (float)MM;
        float mean = ss[0] / n;
        float var = sq[0] / n - mean * mean;
        int o = ch & 127;
        float sc = bn_g[o] * rsqrtf(var + EPSF);
        d_scale2[ch] = sc;
        d_shift2[ch] = bn_b[o] - mean * sc;
    }
}

// ============================================================================
// K5: relu(BN2(y)) then 7 head dot-products per row; warp per row.
// ============================================================================
__global__ __launch_bounds__(256) void k5_heads(
    const float* __restrict__ ce_w, const float* __restrict__ ce_b,
    const float* __restrict__ lwh_w, const float* __restrict__ lwh_b,
    const float* __restrict__ th_w, const float* __restrict__ th_b,
    float* __restrict__ out)
{
    __shared__ float hw[7][128];
    __shared__ float hbias[7];
    const int tid = threadIdx.x;
    for (int f = tid; f < 7 * 128; f += 256) {
        int r = f >> 7, c = f & 127;
        float v = (r < 3) ? ce_w[r * 128 + c]
                : (r < 6) ? lwh_w[(r - 3) * 128 + c]
                          : th_w[c];
        hw[r][c] = v;
    }
    if (tid < 7)
        hbias[tid] = (tid < 3) ? ce_b[tid] : (tid < 6) ? lwh_b[tid - 3] : th_b[0];
    __syncthreads();

    const int wid = tid >> 5, lane = tid & 31;
    const int m = blockIdx.x * 8 + wid;

    float p0 = 0.f, p1 = 0.f, p2 = 0.f, p3 = 0.f, p4 = 0.f, p5 = 0.f, p6 = 0.f;
    #pragma unroll
    for (int k = 0; k < 3; k++) {
        #pragma unroll
        for (int q = 0; q < 4; q++) {
            int o = lane + 32 * q;
            float v = d_y[((size_t)k * MM + m) * 128 + o];
            float xv = fmaxf(0.f, fmaf(d_scale2[k * 128 + o], v, d_shift2[k * 128 + o]));
            if (k == 0) {
                p0 = fmaf(xv, hw[0][o], p0);
                p1 = fmaf(xv, hw[1][o], p1);
                p2 = fmaf(xv, hw[2][o], p2);
            } else if (k == 1) {
                p3 = fmaf(xv, hw[3][o], p3);
                p4 = fmaf(xv, hw[4][o], p4);
                p5 = fmaf(xv, hw[5][o], p5);
            } else {
                p6 = fmaf(xv, hw[6][o], p6);
            }
        }
    }
    float pr[7] = { p0, p1, p2, p3, p4, p5, p6 };
    #pragma unroll
    for (int j = 0; j < 7; j++) {
        float v = pr[j];
        #pragma unroll
        for (int st = 16; st > 0; st >>= 1)
            v += __shfl_down_sync(0xffffffffu, v, st);
        if (lane == 0)
            out[(size_t)m * 7 + j] = v + hbias[j];
    }
}

// ============================================================================
extern "C" void kernel_launch(void* const* d_in, const int* in_sizes, int n_in,
                              void* d_out, int out_size)
{
    const float* x       = (const float*)d_in[0];
    const float* conv1_w = (const float*)d_in[1];
    const float* conv1_b = (const float*)d_in[2];
    const float* bn_g    = (const float*)d_in[3];
    const float* bn_b    = (const float*)d_in[4];
    const float* fc1_w   = (const float*)d_in[5];
    const float* fc1_b   = (const float*)d_in[6];
    const float* ce_w    = (const float*)d_in[7];
    const float* ce_b    = (const float*)d_in[8];
    const float* fc2_w   = (const float*)d_in[9];
    const float* fc2_b   = (const float*)d_in[10];
    const float* lwh_w   = (const float*)d_in[11];
    const float* lwh_b   = (const float*)d_in[12];
    const float* fc3_w   = (const float*)d_in[13];
    const float* fc3_b   = (const float*)d_in[14];
    const float* th_w    = (const float*)d_in[15];
    const float* th_b    = (const float*)d_in[16];

    float* out  = (float*)d_out;          // (B,N,7) flattened
    float* feat = out + (size_t)MM * 7;   // (B,N,128) flattened

    k1_ball_conv<<<NBLK1, 128>>>(x, conv1_w, conv1_b);
    k2_finalize1<<<128, 256>>>(bn_g, bn_b);
    k3_gemm<<<NBLK3, 128>>>(fc1_w, fc1_b, fc2_w, fc2_b, fc3_w, fc3_b, feat);
    k4_finalize2<<<384, 128>>>(bn_g, bn_b);
    k5_heads<<<MM / 8, 256>>>(ce_w, ce_b, lwh_w, lwh_b, th_w, th_b, out);
}